// round 3
// baseline (speedup 1.0000x reference)
#include <cuda_runtime.h>
#include <cuda_bf16.h>

// MoE gather-combine: out[t, :] = sum_k scores[t*K+k] * flat[slots[t*K+k], :]
// Persistent grid-stride kernel with index prefetch: each CTA walks tokens
// with stride gridDim.x, prefetching the NEXT token's slot/score pair while
// the CURRENT token's 4x LDG.128 row loads are in flight. Removes the
// per-wave index->row serial latency of the 1-CTA-per-token version.

__device__ __forceinline__ void stcs_f4(float4* p, float4 v) {
    asm volatile("st.global.cs.v4.f32 [%0], {%1,%2,%3,%4};"
                 :: "l"(p), "f"(v.x), "f"(v.y), "f"(v.z), "f"(v.w) : "memory");
}

__global__ void __launch_bounds__(256)
moe_gather_h2048_persistent(const float* __restrict__ flat,
                            const float* __restrict__ scores,
                            const int* __restrict__ slots,
                            const int* __restrict__ topk_p,
                            float* __restrict__ out,
                            int n_tokens) {
    const int K = topk_p[0];
    const int t0 = threadIdx.x;          // float4 lane 0..255
    const int t1 = threadIdx.x + 256;    // float4 lane 256..511
    const int stride = gridDim.x;

    if (K == 2) {
        int token = blockIdx.x;
        if (token >= n_tokens) return;

        // Prologue: indices for first token.
        int   s0 = __ldg(&slots[token * 2 + 0]);
        int   s1 = __ldg(&slots[token * 2 + 1]);
        float w0 = __ldg(&scores[token * 2 + 0]);
        float w1 = __ldg(&scores[token * 2 + 1]);

        while (true) {
            const int next = token + stride;

            // Issue current token's row loads (4 independent LDG.128/thread).
            const float4* r0 = reinterpret_cast<const float4*>(flat + (size_t)s0 * 2048);
            const float4* r1 = reinterpret_cast<const float4*>(flat + (size_t)s1 * 2048);
            float4 a0 = __ldg(&r0[t0]);
            float4 a1 = __ldg(&r0[t1]);
            float4 b0 = __ldg(&r1[t0]);
            float4 b1 = __ldg(&r1[t1]);

            // Prefetch next token's indices while row loads are in flight.
            int ns0 = 0, ns1 = 0;
            float nw0 = 0.f, nw1 = 0.f;
            if (next < n_tokens) {
                ns0 = __ldg(&slots[next * 2 + 0]);
                ns1 = __ldg(&slots[next * 2 + 1]);
                nw0 = __ldg(&scores[next * 2 + 0]);
                nw1 = __ldg(&scores[next * 2 + 1]);
            }

            // Combine.
            float4 acc0, acc1;
            acc0.x = fmaf(w1, b0.x, w0 * a0.x);
            acc0.y = fmaf(w1, b0.y, w0 * a0.y);
            acc0.z = fmaf(w1, b0.z, w0 * a0.z);
            acc0.w = fmaf(w1, b0.w, w0 * a0.w);
            acc1.x = fmaf(w1, b1.x, w0 * a1.x);
            acc1.y = fmaf(w1, b1.y, w0 * a1.y);
            acc1.z = fmaf(w1, b1.z, w0 * a1.z);
            acc1.w = fmaf(w1, b1.w, w0 * a1.w);

            float4* orow = reinterpret_cast<float4*>(out + (size_t)token * 2048);
            stcs_f4(&orow[t0], acc0);
            stcs_f4(&orow[t1], acc1);

            if (next >= n_tokens) break;
            token = next;
            s0 = ns0; s1 = ns1; w0 = nw0; w1 = nw1;
        }
        return;
    }

    // Generic K path (grid-stride, no prefetch).
    for (int token = blockIdx.x; token < n_tokens; token += stride) {
        float4 acc0 = make_float4(0.f, 0.f, 0.f, 0.f);
        float4 acc1 = make_float4(0.f, 0.f, 0.f, 0.f);
        for (int k = 0; k < K; ++k) {
            const int   slot = __ldg(&slots[token * K + k]);
            const float w    = __ldg(&scores[token * K + k]);
            const float4* row = reinterpret_cast<const float4*>(flat + (size_t)slot * 2048);
            float4 v0 = __ldg(&row[t0]);
            float4 v1 = __ldg(&row[t1]);
            acc0.x = fmaf(w, v0.x, acc0.x);
            acc0.y = fmaf(w, v0.y, acc0.y);
            acc0.z = fmaf(w, v0.z, acc0.z);
            acc0.w = fmaf(w, v0.w, acc0.w);
            acc1.x = fmaf(w, v1.x, acc1.x);
            acc1.y = fmaf(w, v1.y, acc1.y);
            acc1.z = fmaf(w, v1.z, acc1.z);
            acc1.w = fmaf(w, v1.w, acc1.w);
        }
        float4* orow = reinterpret_cast<float4*>(out + (size_t)token * 2048);
        stcs_f4(&orow[t0], acc0);
        stcs_f4(&orow[t1], acc1);
    }
}

// Generic fallback for any hidden (scalar loop within row).
__global__ void moe_gather_generic_kernel(const float* __restrict__ flat,
                                          const float* __restrict__ scores,
                                          const int* __restrict__ slots,
                                          const int* __restrict__ topk_p,
                                          float* __restrict__ out,
                                          int n_tokens, int hidden) {
    const int K = topk_p[0];
    for (int token = blockIdx.x; token < n_tokens; token += gridDim.x) {
        for (int h = threadIdx.x; h < hidden; h += blockDim.x) {
            float acc = 0.f;
            for (int k = 0; k < K; ++k) {
                const int   slot = slots[token * K + k];
                const float w    = scores[token * K + k];
                acc = fmaf(w, flat[(size_t)slot * hidden + h], acc);
            }
            out[(size_t)token * hidden + h] = acc;
        }
    }
}

extern "C" void kernel_launch(void* const* d_in, const int* in_sizes, int n_in,
                              void* d_out, int out_size) {
    const float* flat   = (const float*)d_in[0];   // moe_output, [n_slots, hidden]
    const float* scores = (const float*)d_in[1];   // [n_slots]
    const int*   slots  = (const int*)d_in[2];     // [n_slots]
    const int*   topk_p = (const int*)d_in[3];     // scalar top_k (device)

    const int n_slots = in_sizes[1];
    const int hidden  = in_sizes[0] / n_slots;
    const int n_tokens = out_size / hidden;

    float* out = (float*)d_out;

    if (hidden == 2048) {
        const int SMS = 148, PER_SM = 8;
        int grid = SMS * PER_SM;
        if (grid > n_tokens) grid = n_tokens;
        moe_gather_h2048_persistent<<<grid, 256>>>(flat, scores, slots, topk_p,
                                                   out, n_tokens);
    } else {
        int grid = n_tokens < 1184 ? n_tokens : 1184;
        moe_gather_generic_kernel<<<grid, 256>>>(flat, scores, slots, topk_p,
                                                 out, n_tokens, hidden);
    }
}

// round 5
// speedup vs baseline: 1.0756x; 1.0756x over previous
#include <cuda_runtime.h>
#include <cuda_bf16.h>

// MoE gather-combine: out[t, :] = sum_k scores[t*K+k] * flat[slots[t*K+k], :]
// R2 shape (1 CTA/token, 4x independent LDG.128) + L2 eviction-priority via
// createpolicy/cache_hint: flat rows read with evict_last policy (touched
// ~85MB of flat fits in 126MB L2, re-read every graph replay); outputs
// stored with .cs (evict-first, never re-read).

__device__ __forceinline__ unsigned long long mk_evict_last_policy() {
    unsigned long long pol;
    asm("createpolicy.fractional.L2::evict_last.b64 %0, 1.0;" : "=l"(pol));
    return pol;
}

__device__ __forceinline__ float4 ldg_el_f4(const float4* p, unsigned long long pol) {
    float4 v;
    asm volatile("ld.global.nc.L2::cache_hint.v4.f32 {%0,%1,%2,%3}, [%4], %5;"
                 : "=f"(v.x), "=f"(v.y), "=f"(v.z), "=f"(v.w)
                 : "l"(p), "l"(pol));
    return v;
}

__device__ __forceinline__ void stcs_f4(float4* p, float4 v) {
    asm volatile("st.global.cs.v4.f32 [%0], {%1,%2,%3,%4};"
                 :: "l"(p), "f"(v.x), "f"(v.y), "f"(v.z), "f"(v.w) : "memory");
}

__global__ void __launch_bounds__(256, 8)
moe_gather_h2048_kernel(const float* __restrict__ flat,
                        const float* __restrict__ scores,
                        const int* __restrict__ slots,
                        const int* __restrict__ topk_p,
                        float* __restrict__ out,
                        int n_tokens) {
    const int token = blockIdx.x;
    if (token >= n_tokens) return;
    const int K = topk_p[0];
    const unsigned long long pol = mk_evict_last_policy();

    const int t0 = threadIdx.x;          // float4 lane 0..255
    const int t1 = threadIdx.x + 256;    // float4 lane 256..511
    float4* orow = reinterpret_cast<float4*>(out + (size_t)token * 2048);

    if (K == 2) {
        const int   s0 = __ldg(&slots[token * 2 + 0]);
        const int   s1 = __ldg(&slots[token * 2 + 1]);
        const float w0 = __ldg(&scores[token * 2 + 0]);
        const float w1 = __ldg(&scores[token * 2 + 1]);

        const float4* r0 = reinterpret_cast<const float4*>(flat + (size_t)s0 * 2048);
        const float4* r1 = reinterpret_cast<const float4*>(flat + (size_t)s1 * 2048);

        // 4 independent LDG.128 with evict_last L2 policy.
        float4 a0 = ldg_el_f4(&r0[t0], pol);
        float4 a1 = ldg_el_f4(&r0[t1], pol);
        float4 b0 = ldg_el_f4(&r1[t0], pol);
        float4 b1 = ldg_el_f4(&r1[t1], pol);

        float4 acc0, acc1;
        acc0.x = fmaf(w1, b0.x, w0 * a0.x);
        acc0.y = fmaf(w1, b0.y, w0 * a0.y);
        acc0.z = fmaf(w1, b0.z, w0 * a0.z);
        acc0.w = fmaf(w1, b0.w, w0 * a0.w);
        acc1.x = fmaf(w1, b1.x, w0 * a1.x);
        acc1.y = fmaf(w1, b1.y, w0 * a1.y);
        acc1.z = fmaf(w1, b1.z, w0 * a1.z);
        acc1.w = fmaf(w1, b1.w, w0 * a1.w);

        stcs_f4(&orow[t0], acc0);
        stcs_f4(&orow[t1], acc1);
        return;
    }

    // Generic K path.
    float4 acc0 = make_float4(0.f, 0.f, 0.f, 0.f);
    float4 acc1 = make_float4(0.f, 0.f, 0.f, 0.f);
    for (int k = 0; k < K; ++k) {
        const int   slot = __ldg(&slots[token * K + k]);
        const float w    = __ldg(&scores[token * K + k]);
        const float4* row = reinterpret_cast<const float4*>(flat + (size_t)slot * 2048);
        float4 v0 = ldg_el_f4(&row[t0], pol);
        float4 v1 = ldg_el_f4(&row[t1], pol);
        acc0.x = fmaf(w, v0.x, acc0.x);
        acc0.y = fmaf(w, v0.y, acc0.y);
        acc0.z = fmaf(w, v0.z, acc0.z);
        acc0.w = fmaf(w, v0.w, acc0.w);
        acc1.x = fmaf(w, v1.x, acc1.x);
        acc1.y = fmaf(w, v1.y, acc1.y);
        acc1.z = fmaf(w, v1.z, acc1.z);
        acc1.w = fmaf(w, v1.w, acc1.w);
    }
    stcs_f4(&orow[t0], acc0);
    stcs_f4(&orow[t1], acc1);
}

// Generic fallback for any hidden (scalar loop within row).
__global__ void moe_gather_generic_kernel(const float* __restrict__ flat,
                                          const float* __restrict__ scores,
                                          const int* __restrict__ slots,
                                          const int* __restrict__ topk_p,
                                          float* __restrict__ out,
                                          int n_tokens, int hidden) {
    const int token = blockIdx.x;
    if (token >= n_tokens) return;
    const int K = topk_p[0];

    for (int h = threadIdx.x; h < hidden; h += blockDim.x) {
        float acc = 0.f;
        for (int k = 0; k < K; ++k) {
            const int   slot = slots[token * K + k];
            const float w    = scores[token * K + k];
            acc = fmaf(w, flat[(size_t)slot * hidden + h], acc);
        }
        out[(size_t)token * hidden + h] = acc;
    }
}

extern "C" void kernel_launch(void* const* d_in, const int* in_sizes, int n_in,
                              void* d_out, int out_size) {
    const float* flat   = (const float*)d_in[0];   // moe_output, [n_slots, hidden]
    const float* scores = (const float*)d_in[1];   // [n_slots]
    const int*   slots  = (const int*)d_in[2];     // [n_slots]
    const int*   topk_p = (const int*)d_in[3];     // scalar top_k (device)

    const int n_slots = in_sizes[1];
    const int hidden  = in_sizes[0] / n_slots;
    const int n_tokens = out_size / hidden;

    float* out = (float*)d_out;

    if (hidden == 2048) {
        moe_gather_h2048_kernel<<<n_tokens, 256>>>(flat, scores, slots, topk_p,
                                                   out, n_tokens);
    } else {
        moe_gather_generic_kernel<<<n_tokens, 256>>>(flat, scores, slots, topk_p,
                                                     out, n_tokens, hidden);
    }
}